// round 6
// baseline (speedup 1.0000x reference)
#include <cuda_runtime.h>
#include <math.h>

// Problem constants
#define BB 256
#define PP 5
#define TT 256
#define FF 128
#define HH 512
#define CC 60
#define DD 640      // P*F
#define G4 2048     // 4*H

// Scratch state (device globals: allocation-free per harness rules)
__device__ float g_xw[134217728ULL];   // (T*B, 4H) = 65536 x 2048 fp32
__device__ float g_h[2][BB * HH];      // double-buffered hidden state
__device__ float g_c[BB * HH];         // cell state

// ---------------------------------------------------------------------------
// Packed fp32x2 FMA (SASS FFMA2)
// ---------------------------------------------------------------------------
__device__ __forceinline__ float2 ffma2(float2 a, float2 b, float2 c) {
    unsigned long long ua = *reinterpret_cast<unsigned long long*>(&a);
    unsigned long long ub = *reinterpret_cast<unsigned long long*>(&b);
    unsigned long long uc = *reinterpret_cast<unsigned long long*>(&c);
    unsigned long long ud;
    asm("fma.rn.f32x2 %0, %1, %2, %3;" : "=l"(ud) : "l"(ua), "l"(ub), "l"(uc));
    return *reinterpret_cast<float2*>(&ud);
}

// ---------------------------------------------------------------------------
// Zero initial state
// ---------------------------------------------------------------------------
__global__ void zero_state() {
    int i = blockIdx.x * blockDim.x + threadIdx.x;
    if (i < BB * HH) {
        g_h[0][i] = 0.0f;
        g_c[i]    = 0.0f;
    }
}

// ---------------------------------------------------------------------------
// Phase 1: XW[t*B+b, :] = x_seq[t,b,:] @ Wx + bias  (unchanged — near peak)
// ---------------------------------------------------------------------------
#define KT1 16
__global__ void __launch_bounds__(256, 2)
xw_gemm(const float* __restrict__ X, const float* __restrict__ Wx,
        const float* __restrict__ bvec) {
    __shared__ float a_s[2][KT1][130];
    __shared__ float b_s[2][KT1][128];

    const int tid = threadIdx.x;
    const int by  = blockIdx.y;
    const int n0  = blockIdx.x << 7;
    const int t   = by >> 1;
    const int bb0 = (by & 1) << 7;

    const int tx = tid & 15;
    const int ty = tid >> 4;

    const int lakk = tid & 15;
    const int lamm = tid >> 4;
    const int lbnn = tid & 127;
    const int lbk0 = (tid >> 7) << 3;

    float2 acc[8][4];
#pragma unroll
    for (int j = 0; j < 8; ++j)
#pragma unroll
        for (int p = 0; p < 4; ++p) acc[j][p] = make_float2(0.f, 0.f);

    float ra[8], rb[8];

    auto loadA = [&](int k0) {
        int p = k0 >> 7;
        int f = (k0 & 127) + lakk;
        size_t colofs = (size_t)p * (TT * FF) + (size_t)t * FF + f;
#pragma unroll
        for (int i = 0; i < 8; ++i)
            ra[i] = X[(size_t)(bb0 + lamm + 16 * i) * (PP * TT * FF) + colofs];
    };
    auto loadB = [&](int k0) {
#pragma unroll
        for (int i = 0; i < 8; ++i)
            rb[i] = Wx[(size_t)(k0 + lbk0 + i) * G4 + n0 + lbnn];
    };
    auto stsAB = [&](int buf) {
#pragma unroll
        for (int i = 0; i < 8; ++i) a_s[buf][lakk][lamm + 16 * i] = ra[i];
#pragma unroll
        for (int i = 0; i < 8; ++i) b_s[buf][lbk0 + i][lbnn] = rb[i];
    };

    const int NS = DD / KT1;
    loadA(0); loadB(0);
    stsAB(0);
    __syncthreads();

    for (int s = 0; s < NS; ++s) {
        const int buf = s & 1;
        if (s + 1 < NS) { loadA((s + 1) * KT1); loadB((s + 1) * KT1); }
#pragma unroll
        for (int kk = 0; kk < KT1; ++kk) {
            float2 a01 = *(const float2*)&a_s[buf][kk][ty * 8 + 0];
            float2 a23 = *(const float2*)&a_s[buf][kk][ty * 8 + 2];
            float2 a45 = *(const float2*)&a_s[buf][kk][ty * 8 + 4];
            float2 a67 = *(const float2*)&a_s[buf][kk][ty * 8 + 6];
#pragma unroll
            for (int j = 0; j < 8; ++j) {
                float bv = b_s[buf][kk][tx + 16 * j];
                float2 bb = make_float2(bv, bv);
                acc[j][0] = ffma2(a01, bb, acc[j][0]);
                acc[j][1] = ffma2(a23, bb, acc[j][1]);
                acc[j][2] = ffma2(a45, bb, acc[j][2]);
                acc[j][3] = ffma2(a67, bb, acc[j][3]);
            }
        }
        if (s + 1 < NS) stsAB(buf ^ 1);
        __syncthreads();
    }

    const int mrow = by * 128 + ty * 8;
#pragma unroll
    for (int j = 0; j < 8; ++j) {
        int n = n0 + tx + 16 * j;
        float bn = bvec[n];
#pragma unroll
        for (int p = 0; p < 4; ++p) {
            size_t o = (size_t)(mrow + 2 * p) * G4 + n;
            g_xw[o]      = acc[j][p].x + bn;
            g_xw[o + G4] = acc[j][p].y + bn;
        }
    }
}

// ---------------------------------------------------------------------------
// Phase 2: one LSTM step. 512 threads/block (16 warps = 4/SMSP) to break the
// latency wall seen at occ=12.5%. Tile: 32 batch x 32 ch (x4 gates), grid
// (8,16)=128 blocks. Each thread: 2 batch rows x 1 channel x 4 gates.
//   a_s: [k][m] transposed h tile  -> LDS.64 broadcast (2 variants/warp)
//   b_s: [k][ch*4+gate] interleave -> one LDS.128 = all 4 gate weights
// Inner kk/thread: 1 LDS.64 + 1 LDS.128 + 4 FFMA2.
// ---------------------------------------------------------------------------
#define KT2 32
#define APITCH 36
#define BPITCH 140
__global__ void __launch_bounds__(512, 1)
lstm_step(const float* __restrict__ Wh, const float* __restrict__ tau,
          const float* __restrict__ shift, int t) {
    __shared__ float a_s[2][KT2][APITCH];   // [k][m]
    __shared__ float b_s[2][KT2][BPITCH];   // [k][ch*4+gate]

    const float* __restrict__ hin  = g_h[t & 1];
    float* __restrict__       hout = g_h[(t + 1) & 1];

    const int tid  = threadIdx.x;
    const int m0   = blockIdx.x << 5;        // batch tile base
    const int ch0  = blockIdx.y << 5;        // channel tile base
    const int w    = tid >> 5;               // 0..15
    const int lane = tid & 31;
    const int mg   = lane >> 4;              // 0/1 m-subgroup
    const int chl  = lane & 15;              // channel within half
    const int mb   = (w & 7) * 4 + mg * 2;   // local m base: rows mb, mb+1
    const int chL  = (w >> 3) * 16 + chl;    // local channel 0..31
    const int ch   = ch0 + chL;

    // loader indices
    const int arow = tid & 31;               // a: m row
    const int aks  = tid >> 5;               // a: k pair (2 floats)
    const int bkb  = tid >> 4;               // b: k row (0..31)
    const int bseg = tid & 7;                // b: channel segment (4 ch)
    const int bgp  = (tid >> 3) & 1;         // b: gate pair (0 -> g0,g1 ; 1 -> g2,g3)

    float2 acc[4];                           // [gate], batch pair
#pragma unroll
    for (int q = 0; q < 4; ++q) acc[q] = make_float2(0.f, 0.f);

    float2 ra;
    float4 rb0, rb1;

    auto loadA = [&](int k0) {
        ra = *(const float2*)&hin[(size_t)(m0 + arow) * HH + k0 + aks * 2];
    };
    auto loadB = [&](int k0) {
        const float* wrow = &Wh[(size_t)(k0 + bkb) * G4 + ch0 + bseg * 4];
        rb0 = *(const float4*)&wrow[(2 * bgp + 0) * HH];
        rb1 = *(const float4*)&wrow[(2 * bgp + 1) * HH];
    };
    auto stsA = [&](int buf) {
        a_s[buf][aks * 2 + 0][arow] = ra.x;
        a_s[buf][aks * 2 + 1][arow] = ra.y;
    };
    auto stsB = [&](int buf) {
        // pair-transpose: dest [ch][gate] interleave, gates (2*bgp, 2*bgp+1)
        float* brow = &b_s[buf][bkb][bseg * 16 + 2 * bgp];
        *(float2*)&brow[0]  = make_float2(rb0.x, rb1.x);
        *(float2*)&brow[4]  = make_float2(rb0.y, rb1.y);
        *(float2*)&brow[8]  = make_float2(rb0.z, rb1.z);
        *(float2*)&brow[12] = make_float2(rb0.w, rb1.w);
    };

    const int NS = HH / KT2;   // 16 stages
    loadA(0); loadB(0);
    stsA(0); stsB(0);
    __syncthreads();

    for (int s = 0; s < NS; ++s) {
        const int buf = s & 1;
        if (s + 1 < NS) { loadA((s + 1) * KT2); loadB((s + 1) * KT2); }
#pragma unroll
        for (int kk = 0; kk < KT2; ++kk) {
            float2 a01 = *(const float2*)&a_s[buf][kk][mb];
            float4 bq  = *(const float4*)&b_s[buf][kk][chL * 4];
            acc[0] = ffma2(a01, make_float2(bq.x, bq.x), acc[0]);
            acc[1] = ffma2(a01, make_float2(bq.y, bq.y), acc[1]);
            acc[2] = ffma2(a01, make_float2(bq.z, bq.z), acc[2]);
            acc[3] = ffma2(a01, make_float2(bq.w, bq.w), acc[3]);
        }
        if (s + 1 < NS) { stsA(buf ^ 1); stsB(buf ^ 1); }
        __syncthreads();
    }

    // fused epilogue: gate nonlinearities + phased time gate + state update
    const float tv = tau[ch];
    const float sv = shift[ch];
    float xph = ((float)t - sv) / tv;
    float phi = xph - floorf(xph);
    float kg = (phi < 0.025f) ? (40.0f * phi)
             : (phi < 0.05f)  ? (2.0f - 40.0f * phi)
                              : (0.001f * phi);

    const size_t xwbase = (size_t)t * BB * G4;
#pragma unroll
    for (int r = 0; r < 2; ++r) {
        int m = m0 + mb + r;
        size_t xo = xwbase + (size_t)m * G4 + ch;
        float gi = (r ? acc[0].y : acc[0].x) + g_xw[xo];
        float gf = (r ? acc[1].y : acc[1].x) + g_xw[xo + 512];
        float gg = (r ? acc[2].y : acc[2].x) + g_xw[xo + 1024];
        float go = (r ? acc[3].y : acc[3].x) + g_xw[xo + 1536];
        gi = 1.0f / (1.0f + __expf(-gi));
        gf = 1.0f / (1.0f + __expf(-gf));
        gg = tanhf(gg);
        go = 1.0f / (1.0f + __expf(-go));
        size_t so = (size_t)m * HH + ch;
        float cold = g_c[so];
        float ct = gf * cold + gi * gg;
        float ht = go * tanhf(ct);
        float hold = hin[so];
        g_c[so]  = kg * ct + (1.0f - kg) * cold;
        hout[so] = kg * ht + (1.0f - kg) * hold;
    }
}

// ---------------------------------------------------------------------------
// Phase 3: logits = hT @ fc_w + fc_b; log_softmax over C=60.
// ---------------------------------------------------------------------------
__global__ void head_kernel(const float* __restrict__ fc_w,
                            const float* __restrict__ fc_b,
                            float* __restrict__ out) {
    __shared__ float hrow[HH];
    __shared__ float logits[CC];
    __shared__ float s_lse;
    const int b = blockIdx.x;
    const int tid = threadIdx.x;   // 64 threads

    for (int i = tid; i < HH; i += 64) hrow[i] = g_h[0][(size_t)b * HH + i];
    __syncthreads();

    if (tid < CC) {
        float s = fc_b[tid];
#pragma unroll 8
        for (int k = 0; k < HH; ++k) s += hrow[k] * fc_w[(size_t)k * CC + tid];
        logits[tid] = s;
    }
    __syncthreads();

    if (tid == 0) {
        float mx = -1e30f;
        for (int i = 0; i < CC; ++i) mx = fmaxf(mx, logits[i]);
        float sm = 0.0f;
        for (int i = 0; i < CC; ++i) sm += expf(logits[i] - mx);
        s_lse = mx + logf(sm);
    }
    __syncthreads();

    if (tid < CC) out[(size_t)b * CC + tid] = logits[tid] - s_lse;
}

// ---------------------------------------------------------------------------
// Launch
// ---------------------------------------------------------------------------
extern "C" void kernel_launch(void* const* d_in, const int* in_sizes, int n_in,
                              void* d_out, int out_size) {
    const float* x     = (const float*)d_in[0];
    const float* Wx    = (const float*)d_in[1];
    const float* Wh    = (const float*)d_in[2];
    const float* bias  = (const float*)d_in[3];
    const float* tau   = (const float*)d_in[4];
    const float* shift = (const float*)d_in[5];
    const float* fc_w  = (const float*)d_in[6];
    const float* fc_b  = (const float*)d_in[7];
    float* out = (float*)d_out;

    zero_state<<<(BB * HH + 255) / 256, 256>>>();

    dim3 g1(G4 / 128, (TT * BB) / 128);   // (16, 512)
    xw_gemm<<<g1, 256>>>(x, Wx, bias);

    dim3 g2(BB / 32, HH / 32);            // (8, 16)
    for (int t = 0; t < TT; ++t)
        lstm_step<<<g2, 512>>>(Wh, tau, shift, t);

    head_kernel<<<BB, 64>>>(fc_w, fc_b, out);
}

// round 7
// speedup vs baseline: 1.3806x; 1.3806x over previous
#include <cuda_runtime.h>
#include <math.h>

// Problem constants
#define BB 256
#define PP 5
#define TT 256
#define FF 128
#define HH 512
#define CC 60
#define DD 640      // P*F
#define G4 2048     // 4*H

#define NBLK 128    // persistent grid size (4 x 32)

// Scratch state (device globals: allocation-free per harness rules)
__device__ float g_xw[134217728ULL];   // (T*B, 4H) = 65536 x 2048 fp32
__device__ float g_h[2][BB * HH];      // double-buffered hidden state
__device__ unsigned g_bar;             // software grid barrier counter

// ---------------------------------------------------------------------------
// Packed fp32x2 FMA (SASS FFMA2)
// ---------------------------------------------------------------------------
__device__ __forceinline__ float2 ffma2(float2 a, float2 b, float2 c) {
    unsigned long long ua = *reinterpret_cast<unsigned long long*>(&a);
    unsigned long long ub = *reinterpret_cast<unsigned long long*>(&b);
    unsigned long long uc = *reinterpret_cast<unsigned long long*>(&c);
    unsigned long long ud;
    asm("fma.rn.f32x2 %0, %1, %2, %3;" : "=l"(ud) : "l"(ua), "l"(ub), "l"(uc));
    return *reinterpret_cast<float2*>(&ud);
}

// ---------------------------------------------------------------------------
// Zero initial state + reset grid barrier (runs every launch, orders before
// the persistent kernel on the same stream).
// ---------------------------------------------------------------------------
__global__ void zero_state() {
    int i = blockIdx.x * blockDim.x + threadIdx.x;
    if (i < BB * HH) g_h[0][i] = 0.0f;
    if (i == 0) g_bar = 0u;
}

// ---------------------------------------------------------------------------
// Phase 1: XW[t*B+b, :] = x_seq[t,b,:] @ Wx + bias  (unchanged — near peak)
// ---------------------------------------------------------------------------
#define KT1 16
__global__ void __launch_bounds__(256, 2)
xw_gemm(const float* __restrict__ X, const float* __restrict__ Wx,
        const float* __restrict__ bvec) {
    __shared__ float a_s[2][KT1][130];
    __shared__ float b_s[2][KT1][128];

    const int tid = threadIdx.x;
    const int by  = blockIdx.y;
    const int n0  = blockIdx.x << 7;
    const int t   = by >> 1;
    const int bb0 = (by & 1) << 7;

    const int tx = tid & 15;
    const int ty = tid >> 4;

    const int lakk = tid & 15;
    const int lamm = tid >> 4;
    const int lbnn = tid & 127;
    const int lbk0 = (tid >> 7) << 3;

    float2 acc[8][4];
#pragma unroll
    for (int j = 0; j < 8; ++j)
#pragma unroll
        for (int p = 0; p < 4; ++p) acc[j][p] = make_float2(0.f, 0.f);

    float ra[8], rb[8];

    auto loadA = [&](int k0) {
        int p = k0 >> 7;
        int f = (k0 & 127) + lakk;
        size_t colofs = (size_t)p * (TT * FF) + (size_t)t * FF + f;
#pragma unroll
        for (int i = 0; i < 8; ++i)
            ra[i] = X[(size_t)(bb0 + lamm + 16 * i) * (PP * TT * FF) + colofs];
    };
    auto loadB = [&](int k0) {
#pragma unroll
        for (int i = 0; i < 8; ++i)
            rb[i] = Wx[(size_t)(k0 + lbk0 + i) * G4 + n0 + lbnn];
    };
    auto stsAB = [&](int buf) {
#pragma unroll
        for (int i = 0; i < 8; ++i) a_s[buf][lakk][lamm + 16 * i] = ra[i];
#pragma unroll
        for (int i = 0; i < 8; ++i) b_s[buf][lbk0 + i][lbnn] = rb[i];
    };

    const int NS = DD / KT1;
    loadA(0); loadB(0);
    stsAB(0);
    __syncthreads();

    for (int s = 0; s < NS; ++s) {
        const int buf = s & 1;
        if (s + 1 < NS) { loadA((s + 1) * KT1); loadB((s + 1) * KT1); }
#pragma unroll
        for (int kk = 0; kk < KT1; ++kk) {
            float2 a01 = *(const float2*)&a_s[buf][kk][ty * 8 + 0];
            float2 a23 = *(const float2*)&a_s[buf][kk][ty * 8 + 2];
            float2 a45 = *(const float2*)&a_s[buf][kk][ty * 8 + 4];
            float2 a67 = *(const float2*)&a_s[buf][kk][ty * 8 + 6];
#pragma unroll
            for (int j = 0; j < 8; ++j) {
                float bv = b_s[buf][kk][tx + 16 * j];
                float2 bb = make_float2(bv, bv);
                acc[j][0] = ffma2(a01, bb, acc[j][0]);
                acc[j][1] = ffma2(a23, bb, acc[j][1]);
                acc[j][2] = ffma2(a45, bb, acc[j][2]);
                acc[j][3] = ffma2(a67, bb, acc[j][3]);
            }
        }
        if (s + 1 < NS) stsAB(buf ^ 1);
        __syncthreads();
    }

    const int mrow = by * 128 + ty * 8;
#pragma unroll
    for (int j = 0; j < 8; ++j) {
        int n = n0 + tx + 16 * j;
        float bn = bvec[n];
#pragma unroll
        for (int p = 0; p < 4; ++p) {
            size_t o = (size_t)(mrow + 2 * p) * G4 + n;
            g_xw[o]      = acc[j][p].x + bn;
            g_xw[o + G4] = acc[j][p].y + bn;
        }
    }
}

// ---------------------------------------------------------------------------
// Phase 2 (PERSISTENT): the whole 256-step recurrence in ONE kernel.
//   Grid (4, 32) = 128 blocks, 256 threads. Block owns 64 batch rows x 16
//   channels (x 4 gates). Wh slice [512][16ch x 4g] resident in smem for all
//   steps. c and own-h live in registers. Steps separated by a software
//   grid barrier on g_bar; h exchanged via double-buffered g_h.
//   Thread = 4 rows x 1 ch x 4 gates: per kk 1 LDS.128(a) + 1 LDS.128(w)
//   + 8 FFMA2.
// ---------------------------------------------------------------------------
#define WS_FLOATS (512 * 64)          // Wh slice [k][chl*4+gate]
#define AS_FLOATS (64 * 64)           // one h-chunk buffer [k][row]
#define SMEM_FLOATS (WS_FLOATS + 2 * AS_FLOATS)
#define SMEM_BYTES (SMEM_FLOATS * 4)  // 163840 B

__global__ void __launch_bounds__(256, 1)
plstm_persist(const float* __restrict__ Wh, const float* __restrict__ tau,
              const float* __restrict__ shift) {
    extern __shared__ float smem[];
    float* ws = smem;                    // [512][64]
    float* as = smem + WS_FLOATS;        // [2][64][64]

    const int tid  = threadIdx.x;
    const int m0   = blockIdx.x << 6;    // 4 batch tiles of 64 rows
    const int ch0  = blockIdx.y << 4;    // 32 channel tiles of 16
    const int w    = tid >> 5;
    const int lane = tid & 31;
    const int mg   = lane >> 4;
    const int chl  = lane & 15;
    const int mb   = w * 8 + mg * 4;     // local rows mb..mb+3
    const int ch   = ch0 + chl;

    // ---- prologue: Wh slice -> smem, gate-interleaved [k][chl*4+gate] ----
    for (int idx = tid; idx < 512 * 16; idx += 256) {
        int k    = idx >> 4;
        int seg  = idx & 15;
        int g    = seg >> 2;
        int part = seg & 3;
        float4 v = *(const float4*)&Wh[(size_t)k * G4 + g * HH + ch0 + part * 4];
        float* dst = &ws[k * 64];
        dst[(part * 4 + 0) * 4 + g] = v.x;
        dst[(part * 4 + 1) * 4 + g] = v.y;
        dst[(part * 4 + 2) * 4 + g] = v.z;
        dst[(part * 4 + 3) * 4 + g] = v.w;
    }

    const float tv = tau[ch];
    const float sv = shift[ch];

    // persistent per-thread state
    float creg[4] = {0.f, 0.f, 0.f, 0.f};
    float hreg[4] = {0.f, 0.f, 0.f, 0.f};

    // h-chunk loader indices: row = tid&63, kseg = tid>>6 (16 k each)
    const int hrow = tid & 63;
    const int hks  = (tid >> 6) << 4;
    float4 hv[4];

    __syncthreads();   // ws ready

    for (int t = 0; t < TT; ++t) {
        const float* __restrict__ hin = g_h[t & 1];

        // prefetch this step's xw into registers (hidden under GEMM)
        float xwv[4][4];
        {
            const float* xp = &g_xw[(size_t)t * BB * G4];
#pragma unroll
            for (int r = 0; r < 4; ++r) {
                size_t o = (size_t)(m0 + mb + r) * G4 + ch;
                xwv[0][r] = xp[o];
                xwv[1][r] = xp[o + 512];
                xwv[2][r] = xp[o + 1024];
                xwv[3][r] = xp[o + 1536];
            }
        }

        auto loadH = [&](int k0) {
            const float* hp = &hin[(size_t)(m0 + hrow) * HH + k0 + hks];
            hv[0] = *(const float4*)&hp[0];
            hv[1] = *(const float4*)&hp[4];
            hv[2] = *(const float4*)&hp[8];
            hv[3] = *(const float4*)&hp[12];
        };
        auto stsH = [&](int buf) {
            float* base = &as[buf * AS_FLOATS + hrow];
#pragma unroll
            for (int i = 0; i < 4; ++i) {
                int k = hks + i * 4;
                base[(k + 0) * 64] = hv[i].x;
                base[(k + 1) * 64] = hv[i].y;
                base[(k + 2) * 64] = hv[i].z;
                base[(k + 3) * 64] = hv[i].w;
            }
        };

        float2 acc01[4], acc23[4];
#pragma unroll
        for (int g = 0; g < 4; ++g) {
            acc01[g] = make_float2(0.f, 0.f);
            acc23[g] = make_float2(0.f, 0.f);
        }

        loadH(0);
        stsH(0);
        __syncthreads();

        for (int c = 0; c < 8; ++c) {
            const int buf = c & 1;
            if (c < 7) loadH((c + 1) * 64);
            const float* wsb = &ws[(c * 64) * 64 + chl * 4];
            const float* asb = &as[buf * AS_FLOATS + mb];
#pragma unroll 16
            for (int kk = 0; kk < 64; ++kk) {
                float4 av = *(const float4*)&asb[kk * 64];
                float4 wq = *(const float4*)&wsb[kk * 64];
                float2 a01 = make_float2(av.x, av.y);
                float2 a23 = make_float2(av.z, av.w);
                float2 d;
                d = make_float2(wq.x, wq.x);
                acc01[0] = ffma2(a01, d, acc01[0]);
                acc23[0] = ffma2(a23, d, acc23[0]);
                d = make_float2(wq.y, wq.y);
                acc01[1] = ffma2(a01, d, acc01[1]);
                acc23[1] = ffma2(a23, d, acc23[1]);
                d = make_float2(wq.z, wq.z);
                acc01[2] = ffma2(a01, d, acc01[2]);
                acc23[2] = ffma2(a23, d, acc23[2]);
                d = make_float2(wq.w, wq.w);
                acc01[3] = ffma2(a01, d, acc01[3]);
                acc23[3] = ffma2(a23, d, acc23[3]);
            }
            if (c < 7) stsH(buf ^ 1);
            __syncthreads();
        }

        // ---- fused epilogue ----
        float xph = ((float)t - sv) / tv;
        float phi = xph - floorf(xph);
        float kg = (phi < 0.025f) ? (40.0f * phi)
                 : (phi < 0.05f)  ? (2.0f - 40.0f * phi)
                                  : (0.001f * phi);

        float gv[4][4];
#pragma unroll
        for (int g = 0; g < 4; ++g) {
            gv[g][0] = acc01[g].x;
            gv[g][1] = acc01[g].y;
            gv[g][2] = acc23[g].x;
            gv[g][3] = acc23[g].y;
        }

        float* __restrict__ hout = g_h[(t + 1) & 1];
#pragma unroll
        for (int r = 0; r < 4; ++r) {
            float gi = gv[0][r] + xwv[0][r];
            float gf = gv[1][r] + xwv[1][r];
            float gg = gv[2][r] + xwv[2][r];
            float go = gv[3][r] + xwv[3][r];
            gi = 1.0f / (1.0f + __expf(-gi));
            gf = 1.0f / (1.0f + __expf(-gf));
            gg = tanhf(gg);
            go = 1.0f / (1.0f + __expf(-go));
            float cold = creg[r];
            float ct = gf * cold + gi * gg;
            float ht = go * tanhf(ct);
            creg[r] = kg * ct + (1.0f - kg) * cold;
            float hn = kg * ht + (1.0f - kg) * hreg[r];
            hreg[r] = hn;
            hout[(size_t)(m0 + mb + r) * HH + ch] = hn;
        }

        // ---- grid barrier (skip after final step) ----
        if (t < TT - 1) {
            __syncthreads();
            if (tid == 0) {
                __threadfence();
                atomicAdd(&g_bar, 1u);
                const unsigned target = (unsigned)(t + 1) * NBLK;
                unsigned v;
                do {
                    asm volatile("ld.acquire.gpu.global.u32 %0, [%1];"
                                 : "=r"(v) : "l"(&g_bar) : "memory");
                    if (v >= target) break;
                    __nanosleep(64);
                } while (true);
            }
            __syncthreads();
        }
    }
}

// ---------------------------------------------------------------------------
// Phase 3: logits = hT @ fc_w + fc_b; log_softmax over C=60.
// Final h is in g_h[0] (T=256 even).
// ---------------------------------------------------------------------------
__global__ void head_kernel(const float* __restrict__ fc_w,
                            const float* __restrict__ fc_b,
                            float* __restrict__ out) {
    __shared__ float hrow[HH];
    __shared__ float logits[CC];
    __shared__ float s_lse;
    const int b = blockIdx.x;
    const int tid = threadIdx.x;   // 64 threads

    for (int i = tid; i < HH; i += 64) hrow[i] = g_h[0][(size_t)b * HH + i];
    __syncthreads();

    if (tid < CC) {
        float s = fc_b[tid];
#pragma unroll 8
        for (int k = 0; k < HH; ++k) s += hrow[k] * fc_w[(size_t)k * CC + tid];
        logits[tid] = s;
    }
    __syncthreads();

    if (tid == 0) {
        float mx = -1e30f;
        for (int i = 0; i < CC; ++i) mx = fmaxf(mx, logits[i]);
        float sm = 0.0f;
        for (int i = 0; i < CC; ++i) sm += expf(logits[i] - mx);
        s_lse = mx + logf(sm);
    }
    __syncthreads();

    if (tid < CC) out[(size_t)b * CC + tid] = logits[tid] - s_lse;
}

// ---------------------------------------------------------------------------
// Launch: zero/reset -> XW GEMM -> ONE persistent recurrence kernel -> head.
// ---------------------------------------------------------------------------
extern "C" void kernel_launch(void* const* d_in, const int* in_sizes, int n_in,
                              void* d_out, int out_size) {
    const float* x     = (const float*)d_in[0];
    const float* Wx    = (const float*)d_in[1];
    const float* Wh    = (const float*)d_in[2];
    const float* bias  = (const float*)d_in[3];
    const float* tau   = (const float*)d_in[4];
    const float* shift = (const float*)d_in[5];
    const float* fc_w  = (const float*)d_in[6];
    const float* fc_b  = (const float*)d_in[7];
    float* out = (float*)d_out;

    cudaFuncSetAttribute(plstm_persist,
                         cudaFuncAttributeMaxDynamicSharedMemorySize, SMEM_BYTES);

    zero_state<<<(BB * HH + 255) / 256, 256>>>();

    dim3 g1(G4 / 128, (TT * BB) / 128);   // (16, 512)
    xw_gemm<<<g1, 256>>>(x, Wx, bias);

    dim3 g2(4, 32);                        // 128 persistent blocks
    plstm_persist<<<g2, 256, SMEM_BYTES>>>(Wh, tau, shift);

    head_kernel<<<BB, 64>>>(fc_w, fc_b, out);
}